// round 17
// baseline (speedup 1.0000x reference)
#include <cuda_runtime.h>
#include <cuda_fp16.h>
#include <cstdint>

// LSTMPredictor: B=256, T=1024, H=128, 2-layer LSTM + linear head.
// 32 clusters x 4 CTAs x 256 threads. Layer-pipelined: iteration i computes
// h1(i) and h2(i-1). fp16 mma.sync m16n8k16 (fp32 accum), weights
// register-resident, h half2-packed [k/2][b], MUFU.TANH activations.
// R16: the per-iteration HW cluster barrier is replaced by a warp-distributed
// mbarrier handshake: each warp's lane0 (after __syncwarp + cluster fence)
// arrives on all 4 CTAs' mbarriers (count=32/phase); all threads
// try_wait.parity.acquire.cluster. Pushes are paired: lanes L/L^8 pack their
// two halves into one u32 via shfl, halving DSMEM message count.

namespace {

constexpr int Bt = 256;
constexpr int Tt = 1024;
constexpr int Ht = 128;
constexpr int CL = 4;
constexpr int BC = 8;
constexpr int NTH = 256;

// smem (32-bit words)
constexpr int OFF_HT1 = 0;      // h1: 2 slot x 64 kp x 8 b half2 = 1024 words
constexpr int OFF_HT2 = 1024;   // h2
constexpr int OFF_GA  = 2048;   // gates1 staging [128 r][8 b] fp32
constexpr int OFF_GB  = 3072;   // gates2 staging
constexpr int OFF_BS1 = 4096;   // 128
constexpr int OFF_WX  = 4224;   // 128
constexpr int OFF_BS2 = 4352;   // 128
constexpr int OFF_WO  = 4480;   // 128
constexpr int OFF_X   = 4608;   // 2 slot x 8
constexpr int OFF_BO  = 4624;   // 1
constexpr int OFF_MB  = 4626;   // mbarrier (8 B, 8B-aligned: word idx even)
constexpr int SM_FLOATS = 4628;
constexpr int SM_BYTES = SM_FLOATS * 4;  // ~18.5 KB

__device__ __forceinline__ uint32_t s2u(const void* p) {
    return (uint32_t)__cvta_generic_to_shared(p);
}
__device__ __forceinline__ uint32_t pkh2(float a, float b) {
    __half2 h = __halves2half2(__float2half_rn(a), __float2half_rn(b));
    return *reinterpret_cast<uint32_t*>(&h);
}
// m16n8k16 row.col f16 mma, fp32 accum
__device__ __forceinline__ void mma16(float* d, const uint32_t* a, uint32_t b0,
                                      uint32_t b1) {
    asm volatile(
        "mma.sync.aligned.m16n8k16.row.col.f32.f16.f16.f32 "
        "{%0,%1,%2,%3}, {%4,%5,%6,%7}, {%8,%9}, {%0,%1,%2,%3};"
        : "+f"(d[0]), "+f"(d[1]), "+f"(d[2]), "+f"(d[3])
        : "r"(a[0]), "r"(a[1]), "r"(a[2]), "r"(a[3]), "r"(b0), "r"(b1));
}
__device__ __forceinline__ void st_remote_w(uint32_t laddr, uint32_t peer,
                                            uint32_t v) {
    uint32_t r;
    asm("mapa.shared::cluster.u32 %0, %1, %2;" : "=r"(r) : "r"(laddr), "r"(peer));
    asm volatile("st.shared::cluster.u32 [%0], %1;" ::"r"(r), "r"(v) : "memory");
}
__device__ __forceinline__ void cl_arrive() {
    asm volatile("barrier.cluster.arrive.aligned;" ::: "memory");
}
__device__ __forceinline__ void cl_wait() {
    asm volatile("barrier.cluster.wait.aligned;" ::: "memory");
}
__device__ __forceinline__ void mbar_init(uint32_t mb, uint32_t cnt) {
    asm volatile("mbarrier.init.shared.b64 [%0], %1;" ::"r"(mb), "r"(cnt)
                 : "memory");
}
__device__ __forceinline__ void mbar_arrive_local(uint32_t mb) {
    asm volatile("mbarrier.arrive.shared.b64 _, [%0];" ::"r"(mb) : "memory");
}
__device__ __forceinline__ void mbar_arrive_peer(uint32_t mb, uint32_t peer) {
    uint32_t r;
    asm("mapa.shared::cluster.u32 %0, %1, %2;" : "=r"(r) : "r"(mb), "r"(peer));
    asm volatile("mbarrier.arrive.shared::cluster.b64 _, [%0];" ::"r"(r)
                 : "memory");
}
__device__ __forceinline__ void mbar_wait_cl(uint32_t mb, uint32_t par) {
    uint32_t done;
    asm volatile(
        "{\n\t.reg .pred p;\n\t"
        "mbarrier.try_wait.parity.acquire.cluster.shared::cta.b64 p, [%1], %2;\n\t"
        "selp.b32 %0, 1, 0, p;\n\t}"
        : "=r"(done) : "r"(mb), "r"(par) : "memory");
    if (!done) {
        asm volatile(
            "{\n\t.reg .pred P1;\n\t"
            "W_%=:\n\t"
            "mbarrier.try_wait.parity.acquire.cluster.shared::cta.b64 P1, [%0], %1, 0x989680;\n\t"
            "@P1 bra.uni D_%=;\n\t"
            "bra.uni W_%=;\n\t"
            "D_%=:\n\t}"
            :: "r"(mb), "r"(par) : "memory");
    }
}
// MUFU.TANH-based activations
__device__ __forceinline__ float tanh_mufu(float x) {
    float r;
    asm("tanh.approx.f32 %0, %1;" : "=f"(r) : "f"(x));
    return r;
}
__device__ __forceinline__ float sigf(float x) {
    return fmaf(tanh_mufu(0.5f * x), 0.5f, 0.5f);
}

__global__ void __launch_bounds__(NTH, 1) lstm_mma_kernel(
    const float* __restrict__ x, const float* __restrict__ Wih1,
    const float* __restrict__ Whh1, const float* __restrict__ bih1,
    const float* __restrict__ bhh1, const float* __restrict__ Wih2,
    const float* __restrict__ Whh2, const float* __restrict__ bih2,
    const float* __restrict__ bhh2, const float* __restrict__ Wout,
    const float* __restrict__ bout, float* __restrict__ out) {
    extern __shared__ float sm[];
    uint32_t* hH1 = reinterpret_cast<uint32_t*>(sm + OFF_HT1);
    uint32_t* hH2 = reinterpret_cast<uint32_t*>(sm + OFF_HT2);
    float* gbA = sm + OFF_GA;
    float* gbB = sm + OFF_GB;
    float* bs1s = sm + OFF_BS1;
    float* wxs = sm + OFF_WX;
    float* bs2s = sm + OFF_BS2;
    float* wos = sm + OFF_WO;
    float* xS = sm + OFF_X;
    float* boS = sm + OFF_BO;

    const int tid = threadIdx.x;
    const int lane = tid & 31;
    const int warp = tid >> 5;
    const int rank = blockIdx.x & 3;
    const int bbase = (blockIdx.x >> 2) * BC;
    const int U0 = rank * 32;
    const uint32_t MB = s2u(sm + OFF_MB);

    // ---- MMA fragment coordinates (m16n8k16) ----
    const int q = lane & 3;
    const int g8 = lane >> 2;
    const int lr0 = warp * 16 + g8;
    const int lr1 = lr0 + 8;
    const int qg = q * 8 + g8;  // B-frag word offset within kt block
    const int G0 = ((lr0 >> 5) << 7) + U0 + (lr0 & 31);
    const int G1 = G0 + 8;

    // ---- weights -> registers as fp16 A-fragments (8 kt x 4 regs each) ----
    uint32_t w1[32], w2h[32], w2i[32];
#pragma unroll
    for (int kt = 0; kt < 8; ++kt) {
        const int k0 = kt * 16 + q * 2;
        w1[kt * 4 + 0] = pkh2(Whh1[G0 * Ht + k0], Whh1[G0 * Ht + k0 + 1]);
        w1[kt * 4 + 1] = pkh2(Whh1[G1 * Ht + k0], Whh1[G1 * Ht + k0 + 1]);
        w1[kt * 4 + 2] = pkh2(Whh1[G0 * Ht + k0 + 8], Whh1[G0 * Ht + k0 + 9]);
        w1[kt * 4 + 3] = pkh2(Whh1[G1 * Ht + k0 + 8], Whh1[G1 * Ht + k0 + 9]);
        w2h[kt * 4 + 0] = pkh2(Whh2[G0 * Ht + k0], Whh2[G0 * Ht + k0 + 1]);
        w2h[kt * 4 + 1] = pkh2(Whh2[G1 * Ht + k0], Whh2[G1 * Ht + k0 + 1]);
        w2h[kt * 4 + 2] = pkh2(Whh2[G0 * Ht + k0 + 8], Whh2[G0 * Ht + k0 + 9]);
        w2h[kt * 4 + 3] = pkh2(Whh2[G1 * Ht + k0 + 8], Whh2[G1 * Ht + k0 + 9]);
        w2i[kt * 4 + 0] = pkh2(Wih2[G0 * Ht + k0], Wih2[G0 * Ht + k0 + 1]);
        w2i[kt * 4 + 1] = pkh2(Wih2[G1 * Ht + k0], Wih2[G1 * Ht + k0 + 1]);
        w2i[kt * 4 + 2] = pkh2(Wih2[G0 * Ht + k0 + 8], Wih2[G0 * Ht + k0 + 9]);
        w2i[kt * 4 + 3] = pkh2(Wih2[G1 * Ht + k0 + 8], Wih2[G1 * Ht + k0 + 9]);
    }

    // ---- biases / small vectors into SMEM; zero h slots; mbarrier init ----
    for (int r = tid; r < 128; r += NTH) {
        const int G = ((r >> 5) << 7) + U0 + (r & 31);
        bs1s[r] = bih1[G] + bhh1[G];
        wxs[r] = Wih1[G];
        bs2s[r] = bih2[G] + bhh2[G];
        wos[r] = Wout[r];
    }
    for (int i = tid; i < 2048; i += NTH) sm[OFF_HT1 + i] = 0.0f;  // h tiles
    if (tid == 0) {
        boS[0] = bout[0];
        mbar_init(MB, 32);  // 8 warps x 4 CTAs per phase
    }
    if (tid < BC) xS[tid] = x[(bbase + tid) * Tt + 0];  // x(0) -> slot 0
    __syncthreads();
    cl_arrive();
    cl_wait();  // peers' h buffers zeroed + mbarriers initialized

    const uint32_t h1u = s2u(hH1);
    const uint32_t h2u = s2u(hH2);
    const uint32_t p1 = (rank + 1) & 3, p2r = (rank + 2) & 3, p3 = (rank + 3) & 3;
    const float boutr = boS[0];

    // epilogue mapping: bb = tid&7, unit gU = U0 + (tid>>3)
    const int bb = tid & 7;
    const int uu = tid >> 3;
    const int gU = U0 + uu;
    const bool hi_half = (gU & 1);  // odd unit -> upper half of word
    // word offset (bytes) of the packed half2 for this unit pair
    const uint32_t hword = (uint32_t)(((gU >> 1) * 8 + bb) * 4);
    const float bA0 = bs1s[0 * 32 + uu], bA1 = bs1s[1 * 32 + uu];
    const float bA2 = bs1s[2 * 32 + uu], bA3 = bs1s[3 * 32 + uu];
    const float wx0 = wxs[0 * 32 + uu], wx1 = wxs[1 * 32 + uu];
    const float wx2 = wxs[2 * 32 + uu], wx3 = wxs[3 * 32 + uu];
    const float bB0 = bs2s[0 * 32 + uu], bB1 = bs2s[1 * 32 + uu];
    const float bB2 = bs2s[2 * 32 + uu], bB3 = bs2s[3 * 32 + uu];
    // output-head weights (warps 6,7)
    const float wo0 = wos[2 * lane], wo1 = wos[2 * lane + 1];
    const float wo2 = wos[2 * lane + 64], wo3 = wos[2 * lane + 65];

    float c1 = 0.0f, c2 = 0.0f;

    // iteration i: h1(i) -> hH1 slot i&1 ; h2(i-1) -> hH2 slot (i-1)&1
    for (int i = 0; i <= Tt; ++i) {
        const int p = i & 1;
        const int pp = p ^ 1;
        const bool doA = (i < Tt);
        const bool doB = (i > 0);

        const uint32_t* h1p = hH1 + pp * 512;  // h1(i-1)
        const uint32_t* h2p = hH2 + p * 512;   // h2(i-2)

        // ===== all MMAs up front: D1 = W1@h1 ; D2 = W2h@h2 + W2i@h1 =====
        float d1a[4] = {0, 0, 0, 0}, d1b[4] = {0, 0, 0, 0};
        float d2a[4] = {0, 0, 0, 0}, d2b[4] = {0, 0, 0, 0};
        float d2c[4] = {0, 0, 0, 0}, d2d[4] = {0, 0, 0, 0};
        if (doA && doB) {
#pragma unroll
            for (int kt = 0; kt < 8; ++kt) {
                const uint32_t b0 = h1p[kt * 64 + qg];
                const uint32_t b1 = h1p[kt * 64 + 32 + qg];
                const uint32_t e0 = h2p[kt * 64 + qg];
                const uint32_t e1 = h2p[kt * 64 + 32 + qg];
                mma16((kt & 1) ? d1b : d1a, &w1[kt * 4], b0, b1);
                mma16((kt & 1) ? d2b : d2a, &w2h[kt * 4], e0, e1);
                mma16((kt & 1) ? d2d : d2c, &w2i[kt * 4], b0, b1);
            }
        } else if (doA) {  // i == 0
#pragma unroll
            for (int kt = 0; kt < 8; ++kt) {
                const uint32_t b0 = h1p[kt * 64 + qg];
                const uint32_t b1 = h1p[kt * 64 + 32 + qg];
                mma16((kt & 1) ? d1b : d1a, &w1[kt * 4], b0, b1);
            }
        } else {  // i == Tt
#pragma unroll
            for (int kt = 0; kt < 8; ++kt) {
                const uint32_t b0 = h1p[kt * 64 + qg];
                const uint32_t b1 = h1p[kt * 64 + 32 + qg];
                const uint32_t e0 = h2p[kt * 64 + qg];
                const uint32_t e1 = h2p[kt * 64 + 32 + qg];
                mma16((kt & 1) ? d2b : d2a, &w2h[kt * 4], e0, e1);
                mma16((kt & 1) ? d2d : d2c, &w2i[kt * 4], b0, b1);
            }
        }
        // stage both gate tiles, then ONE sync
        if (doA) {
            float2* gA2 = reinterpret_cast<float2*>(gbA);
            gA2[lr0 * 4 + q] = make_float2(d1a[0] + d1b[0], d1a[1] + d1b[1]);
            gA2[lr1 * 4 + q] = make_float2(d1a[2] + d1b[2], d1a[3] + d1b[3]);
        }
        if (doB) {
            float2* gB2 = reinterpret_cast<float2*>(gbB);
            gB2[lr0 * 4 + q] =
                make_float2(d2a[0] + d2b[0] + d2c[0] + d2d[0],
                            d2a[1] + d2b[1] + d2c[1] + d2d[1]);
            gB2[lr1 * 4 + q] =
                make_float2(d2a[2] + d2b[2] + d2c[2] + d2d[2],
                            d2a[3] + d2b[3] + d2c[3] + d2d[3]);
        }
        __syncthreads();

        // ===== both epilogues back-to-back; paired u32 pushes =====
        if (doA) {
            const float xv = xS[p * 8 + bb];
            const float gi = gbA[(0 * 32 + uu) * 8 + bb] + bA0 + xv * wx0;
            const float gf = gbA[(1 * 32 + uu) * 8 + bb] + bA1 + xv * wx1;
            const float gg = gbA[(2 * 32 + uu) * 8 + bb] + bA2 + xv * wx2;
            const float go = gbA[(3 * 32 + uu) * 8 + bb] + bA3 + xv * wx3;
            c1 = sigf(gf) * c1 + sigf(gi) * tanh_mufu(gg);
            const float h1f = sigf(go) * tanh_mufu(c1);
            const __half h1h = __float2half_rn(h1f);
            uint32_t hb = (uint32_t)*reinterpret_cast<const unsigned short*>(&h1h);
            const uint32_t prt = __shfl_xor_sync(0xffffffffu, hb, 8);
            if (!hi_half) {
                const uint32_t wv = hb | (prt << 16);
                const uint32_t la = h1u + (uint32_t)p * 2048u + hword;
                asm volatile("st.shared.u32 [%0], %1;" ::"r"(la), "r"(wv)
                             : "memory");
                st_remote_w(la, p1, wv);
                st_remote_w(la, p2r, wv);
                st_remote_w(la, p3, wv);
            }
        }
        if (doB) {
            const float gi = gbB[(0 * 32 + uu) * 8 + bb] + bB0;
            const float gf = gbB[(1 * 32 + uu) * 8 + bb] + bB1;
            const float gg = gbB[(2 * 32 + uu) * 8 + bb] + bB2;
            const float go = gbB[(3 * 32 + uu) * 8 + bb] + bB3;
            c2 = sigf(gf) * c2 + sigf(gi) * tanh_mufu(gg);
            const float h2f = sigf(go) * tanh_mufu(c2);
            const __half h2h = __float2half_rn(h2f);
            uint32_t hb = (uint32_t)*reinterpret_cast<const unsigned short*>(&h2h);
            const uint32_t prt = __shfl_xor_sync(0xffffffffu, hb, 8);
            if (!hi_half) {
                const uint32_t wv = hb | (prt << 16);
                const uint32_t la = h2u + (uint32_t)pp * 2048u + hword;
                asm volatile("st.shared.u32 [%0], %1;" ::"r"(la), "r"(wv)
                             : "memory");
                st_remote_w(la, p1, wv);
                st_remote_w(la, p2r, wv);
                st_remote_w(la, p3, wv);
            }
        }

        // ===== warp-distributed mbarrier handshake (replaces HW barrier) ====
        __syncwarp();
        if (lane == 0) {
            asm volatile("fence.acq_rel.cluster;" ::: "memory");
            mbar_arrive_peer(MB, p1);
            mbar_arrive_peer(MB, p2r);
            mbar_arrive_peer(MB, p3);
            mbar_arrive_local(MB);
        }
        if (tid < BC && doA) {  // x prefetch while waiting
            xS[pp * 8 + tid] =
                (i + 1 < Tt) ? x[(bbase + tid) * Tt + (i + 1)] : 0.0f;
        }
        mbar_wait_cl(MB, (uint32_t)(i & 1));

        // ===== output(i-1): warps 6,7 (overlaps next iteration's MMA) =====
        if (doB && warp >= 6) {
            const int bl = rank * 2 + (warp - 6);
            const uint32_t* h2c = hH2 + pp * 512;
            const __half2 ha =
                *reinterpret_cast<const __half2*>(&h2c[lane * 8 + bl]);
            const __half2 hb2 =
                *reinterpret_cast<const __half2*>(&h2c[(lane + 32) * 8 + bl]);
            const float2 fa = __half22float2(ha);
            const float2 fb = __half22float2(hb2);
            float s = fa.x * wo0 + fa.y * wo1 + fb.x * wo2 + fb.y * wo3;
            s += __shfl_xor_sync(0xffffffffu, s, 16);
            s += __shfl_xor_sync(0xffffffffu, s, 8);
            s += __shfl_xor_sync(0xffffffffu, s, 4);
            s += __shfl_xor_sync(0xffffffffu, s, 2);
            s += __shfl_xor_sync(0xffffffffu, s, 1);
            if (lane == 0) out[(bbase + bl) * Tt + (i - 1)] = s + boutr;
        }
    }

    // exit safety: no CTA leaves while peers could still target its smem
    cl_arrive();
    cl_wait();
}

}  // namespace

extern "C" void kernel_launch(void* const* d_in, const int* in_sizes, int n_in,
                              void* d_out, int out_size) {
    (void)in_sizes;
    (void)n_in;
    (void)out_size;
    const float* x = (const float*)d_in[0];
    const float* Wih1 = (const float*)d_in[1];
    const float* Whh1 = (const float*)d_in[2];
    const float* bih1 = (const float*)d_in[3];
    const float* bhh1 = (const float*)d_in[4];
    const float* Wih2 = (const float*)d_in[5];
    const float* Whh2 = (const float*)d_in[6];
    const float* bih2 = (const float*)d_in[7];
    const float* bhh2 = (const float*)d_in[8];
    const float* Wout = (const float*)d_in[9];
    const float* bout = (const float*)d_in[10];
    float* out = (float*)d_out;

    cudaFuncSetAttribute(lstm_mma_kernel,
                         cudaFuncAttributeMaxDynamicSharedMemorySize, SM_BYTES);

    cudaLaunchConfig_t cfg = {};
    cfg.gridDim = dim3((Bt / BC) * CL, 1, 1);  // 128 CTAs = 32 clusters of 4
    cfg.blockDim = dim3(NTH, 1, 1);
    cfg.dynamicSmemBytes = SM_BYTES;
    cfg.stream = 0;
    cudaLaunchAttribute attrs[1];
    attrs[0].id = cudaLaunchAttributeClusterDimension;
    attrs[0].val.clusterDim.x = CL;
    attrs[0].val.clusterDim.y = 1;
    attrs[0].val.clusterDim.z = 1;
    cfg.attrs = attrs;
    cfg.numAttrs = 1;

    cudaLaunchKernelEx(&cfg, lstm_mma_kernel, x, Wih1, Whh1, bih1, bhh1, Wih2,
                       Whh2, bih2, bhh2, Wout, bout, out);
}